// round 17
// baseline (speedup 1.0000x reference)
#include <cuda_runtime.h>

#define NBATCH 4
#define NTOK   4096
#define DDIM   16
#define NB     64                    /* bins */
#define XLO    (-6.0f)
#define BINW   0.1875f               /* 12/64, exact in fp32 */
#define INVW   (64.0f / 12.0f)
#define L2E    1.44269504088896f
#define GX     32                    /* blocks per batch (both kernels) */
#define NTHR   128                   /* hist: one thread per value */
#define NTHR2  256                   /* main: 2 threads per row */
#define RPB    (NTOK / GX)           /* 128 rows per block */
#define NMOM   6

// Parity double-buffered FINAL per-batch histograms, bin-major float4 layout:
//   g_hA[p][b][bin] = (n, M1, M2, M3),  g_hB[p][b][bin] = (M4, M5, 0, 0)
// Buffer p is pre-zeroed by the previous same-parity hist launch.
__device__ float4   g_hA[2][NBATCH][NB];
__device__ float4   g_hB[2][NBATCH][NB];
__device__ unsigned g_tick_h;        // hist launch-ticket counter
__device__ unsigned g_par;           // parity published by hist for main (plain word)

__device__ __forceinline__ float ex2f(float v) {
    float r;
    asm("ex2.approx.ftz.f32 %0, %1;" : "=f"(r) : "f"(v));
    return r;
}

// ---------------- kernel 1: smem partial hist -> global RED.ADD (bin-major) ----------------
__global__ __launch_bounds__(NTHR, 1)
void hist_kernel(const float* __restrict__ x)
{
    __shared__ float h[NMOM][NB];
    __shared__ unsigned s_ticket;

    const int b   = blockIdx.y;
    const int blk = blockIdx.x;
    const int tid = threadIdx.x;

    if (tid == 0) s_ticket = atomicAdd(&g_tick_h, 1u);

    // this CTA's 128 values (L2-resident after first replay)
    const float v = x[b * NTOK + blk * RPB + tid];

    #pragma unroll
    for (int i = tid; i < NMOM * NB; i += NTHR)
        (&h[0][0])[i] = 0.f;
    __syncthreads();

    const int p = (int)((s_ticket >> 7) & 1u);   // launch parity (128 CTAs/launch)
    if (tid == 0) g_par = (unsigned)p;           // publish for main (benign dup writes)

    // ---- smem moment histogram: 768 spread lane-atomics (proven fast) ----
    {
        int k = __float2int_rz((v - XLO) * INVW);
        k = max(0, min(NB - 1, k));
        float bc = fmaf((float)k + 0.5f, BINW, XLO);
        float d  = v - bc;
        float d2 = d * d;
        float d3 = d2 * d;
        atomicAdd(&h[0][k], 1.0f);
        atomicAdd(&h[1][k], d);
        atomicAdd(&h[2][k], d2);
        atomicAdd(&h[3][k], d3);
        atomicAdd(&h[4][k], d2 * d2);
        atomicAdd(&h[5][k], d3 * d2);
    }
    __syncthreads();

    // ---- fire-and-forget REDG into bin-major final layout ----
    // 384 meaningful floats: moment m, bin j -> component m of g_hA/g_hB[j]
    #pragma unroll
    for (int i = 0; i < 3; i++) {
        int idx = tid + i * NTHR;                // 0..383
        int m   = idx >> 6;                      // moment 0..5
        int j   = idx & 63;                      // bin
        float val = h[m][j];
        float* dst = (m < 4)
            ? (reinterpret_cast<float*>(&g_hA[p][b][j]) + m)
            : (reinterpret_cast<float*>(&g_hB[p][b][j]) + (m - 4));
        atomicAdd(dst, val);
    }

    // ---- zero the OTHER parity buffer for the next launch (redundant, harmless) ----
    if (tid < 2 * NB) {
        const float4 z = make_float4(0.f, 0.f, 0.f, 0.f);
        if (tid < NB) g_hA[1 - p][b][tid] = z;
        else          g_hB[1 - p][b][tid - NB] = z;
    }
}

// ---------------- kernel 2: hoisted hist load + per-row sums ----------------
__global__ __launch_bounds__(NTHR2, 1)
void main_kernel(const float* __restrict__ x,
                 const float* __restrict__ wq,
                 const float* __restrict__ wk,
                 const float* __restrict__ wv,
                 const float* __restrict__ wo,
                 float* __restrict__ out)
{
    __shared__ float4 sha[NB];           // (n, M1, M2, M3)
    __shared__ float4 shb[NB];           // (M4, M5, -, -)
    __shared__ float  sr0[NTHR2];        // phase-C partial s0
    __shared__ float  sr1[NTHR2];        // phase-C partial s1

    const int b    = blockIdx.y;
    const int blk  = blockIdx.x;
    const int tid  = threadIdx.x;
    const int col  = tid & 127;          // row index within block
    const int half = tid >> 7;           // 0 or 1

    // ======== kernel top: issue ALL loads immediately ========

    // parity (plain LDG; valid by node-boundary ordering), then histogram
    const unsigned p = *(volatile unsigned*)&g_par;
    if (tid < 2 * NB) {
        float4 f = (tid < NB) ? __ldcg(&g_hA[p][b][tid])
                              : __ldcg(&g_hB[p][b][tid - NB]);
        if (tid < NB) sha[tid] = f;
        else          shb[tid - NB] = f;
    }

    // this thread's row value (overlaps the histogram L2 trip)
    const float v = x[b * NTOK + blk * RPB + col];

    // tiny dot products (redundant per thread, L1 broadcast)
    float c = 0.f, g = 0.f;
    #pragma unroll
    for (int i = 0; i < DDIM; i++) {
        c = fmaf(wq[i], wk[i], c);
        g = fmaf(wv[i], wo[i], g);
    }
    c *= 0.25f;   // 1/sqrt(ATTN_DIM), TAU = 1

    // per-row exponent machinery (independent of histogram)
    const float t  = c * v;
    const float u2 = 0.5f * t * t;
    const float u3 = u2 * t * (1.f / 3.f);
    const float u4 = u3 * t * 0.25f;
    const float u5 = u4 * t * 0.2f;
    const float A  = t * L2E;
    const float C0 = -fabsf(A) * 6.0f;           // global max-shift: arg <= 0
    const int   k0 = half * (NB / 2);
    float bb = fmaf((float)k0 + 0.5f, BINW, XLO);
    float e  = ex2f(fmaf(A, bb, C0));
    const float f = ex2f(A * BINW);

    __syncthreads();                              // sha/shb ready

    // ---- phase C: each thread handles 32 bins of row 'col' ----
    {
        float s0 = 0.f, s1 = 0.f;

        #pragma unroll
        for (int k = 0; k < NB / 2; k++) {
            float4 ma = sha[k0 + k];             // warp-uniform broadcast
            float4 mb = shb[k0 + k];
            float P = fmaf(t,  ma.y, ma.x);
            P       = fmaf(u2, ma.z, P);
            P       = fmaf(u3, ma.w, P);
            P       = fmaf(u4, mb.x, P);
            P       = fmaf(u5, mb.y, P);
            float Q = fmaf(t,  ma.z, ma.y);
            Q       = fmaf(u2, ma.w, Q);
            Q       = fmaf(u3, mb.x, Q);
            Q       = fmaf(u4, mb.y, Q);
            float r = fmaf(bb, P, Q);
            s0 = fmaf(e, P, s0);
            s1 = fmaf(e, r, s1);
            e *= f;
            bb += BINW;
        }

        sr0[tid] = s0;
        sr1[tid] = s1;
    }
    __syncthreads();

    if (half == 0) {
        float S0 = sr0[col] + sr0[col + 128];
        float S1 = sr1[col] + sr1[col + 128];
        out[b * NTOK + blk * RPB + col] = g * S1 / S0;
    }
}

extern "C" void kernel_launch(void* const* d_in, const int* in_sizes, int n_in,
                              void* d_out, int out_size)
{
    const float* x  = (const float*)d_in[0];
    const float* wq = (const float*)d_in[1];
    const float* wk = (const float*)d_in[2];
    const float* wv = (const float*)d_in[3];
    const float* wo = (const float*)d_in[4];
    float* out = (float*)d_out;

    hist_kernel<<<dim3(GX, NBATCH), NTHR>>>(x);
    main_kernel<<<dim3(GX, NBATCH), NTHR2>>>(x, wq, wk, wv, wo, out);
}